// round 4
// baseline (speedup 1.0000x reference)
#include <cuda_runtime.h>
#include <cstdint>

#define CELLS (1 << 21)                   // 128^3 coarse cells, 21-bit key
#define SCAN_CHUNK 2048                   // 256 thr x 8
#define SCAN_BLOCKS (CELLS / SCAN_CHUNK)  // 1024
#define MAXN 524288

__device__ __align__(16) unsigned int g_mark[CELLS];
__device__ __align__(16) unsigned int g_rank[CELLS];
__device__ unsigned int g_bsum[SCAN_BLOCKS];
__device__ unsigned int g_numu;
__device__ int g_winner[MAXN * 8];

// ---------------------------------------------------------------------------
__global__ void markK(const int* __restrict__ coords, int n) {
    int i = blockIdx.x * blockDim.x + threadIdx.x;
    if (i >= n) return;
    int cx = coords[3 * i + 0] >> 1;
    int cy = coords[3 * i + 1] >> 1;
    int cz = coords[3 * i + 2] >> 1;
    g_mark[((unsigned)cx << 14) | ((unsigned)cy << 7) | (unsigned)cz] = 1u;
}

// Stage A: per-block sums (warp-shuffle reduce, one barrier)
__global__ void scanA() {
    int t = threadIdx.x, lane = t & 31, warp = t >> 5;
    int base = blockIdx.x * SCAN_CHUNK + t * 8;
    const uint4* p = (const uint4*)&g_mark[base];
    uint4 a = p[0], b = p[1];
    unsigned sum = a.x + a.y + a.z + a.w + b.x + b.y + b.z + b.w;
#pragma unroll
    for (int o = 16; o > 0; o >>= 1) sum += __shfl_down_sync(0xFFFFFFFFu, sum, o);
    __shared__ unsigned ws[8];
    if (lane == 0) ws[warp] = sum;
    __syncthreads();
    if (t == 0) {
        unsigned s = 0;
#pragma unroll
        for (int i = 0; i < 8; i++) s += ws[i];
        g_bsum[blockIdx.x] = s;
    }
}

// Stage B: exclusive scan of 1024 block sums (single block, shuffle-based)
__global__ void scanB() {
    int t = threadIdx.x, lane = t & 31, warp = t >> 5;
    unsigned v = g_bsum[t];
    unsigned x = v;
#pragma unroll
    for (int o = 1; o < 32; o <<= 1) {
        unsigned y = __shfl_up_sync(0xFFFFFFFFu, x, o);
        if (lane >= o) x += y;
    }
    __shared__ unsigned ws[32];
    if (lane == 31) ws[warp] = x;
    __syncthreads();
    if (warp == 0) {
        unsigned w = ws[lane];
#pragma unroll
        for (int o = 1; o < 32; o <<= 1) {
            unsigned y = __shfl_up_sync(0xFFFFFFFFu, w, o);
            if (lane >= o) w += y;
        }
        ws[lane] = w;
    }
    __syncthreads();
    unsigned incl = (warp ? ws[warp - 1] : 0u) + x;
    g_bsum[t] = incl - v;               // exclusive
    if (t == 1023) g_numu = incl;
}

// Stage C: per-element exclusive prefix -> g_rank; ALSO emits the sorted
// unique coarse coords directly (occupancy + rank are already in registers).
__global__ void scanC(float* __restrict__ outc) {
    int t = threadIdx.x, lane = t & 31, warp = t >> 5;
    int base = blockIdx.x * SCAN_CHUNK + t * 8;
    const uint4* p = (const uint4*)&g_mark[base];
    uint4 a = p[0], b = p[1];
    unsigned e[8] = {a.x, a.y, a.z, a.w, b.x, b.y, b.z, b.w};
    unsigned sum = 0;
#pragma unroll
    for (int i = 0; i < 8; i++) sum += e[i];
    unsigned x = sum;
#pragma unroll
    for (int o = 1; o < 32; o <<= 1) {
        unsigned y = __shfl_up_sync(0xFFFFFFFFu, x, o);
        if (lane >= o) x += y;
    }
    __shared__ unsigned ws[8];
    if (lane == 31) ws[warp] = x;
    __syncthreads();
    if (t < 8) {
        unsigned w = ws[t];
#pragma unroll
        for (int o = 1; o < 8; o <<= 1) {
            unsigned y = __shfl_up_sync(0x000000FFu, w, o);
            if (t >= o) w += y;
        }
        ws[t] = w;
    }
    __syncthreads();
    unsigned run = (warp ? ws[warp - 1] : 0u) + (x - sum) + g_bsum[blockIdx.x];

    unsigned r[8];
#pragma unroll
    for (int i = 0; i < 8; i++) {
        r[i] = run;
        if (e[i]) {
            unsigned c = (unsigned)(base + i);
            outc[run * 3 + 0] = (float)((c >> 14) & 127);
            outc[run * 3 + 1] = (float)((c >> 7) & 127);
            outc[run * 3 + 2] = (float)(c & 127);
        }
        run += e[i];
    }
    uint4* q = (uint4*)&g_rank[base];
    q[0] = make_uint4(r[0], r[1], r[2], r[3]);
    q[1] = make_uint4(r[4], r[5], r[6], r[7]);
}

// Fill only the padding rows (row >= numu) with -1
__global__ void fillTailK(float* __restrict__ outc, int n) {
    int r = blockIdx.x * blockDim.x + threadIdx.x;
    if (r >= n || (unsigned)r < g_numu) return;
    outc[r * 3 + 0] = -1.0f;
    outc[r * 3 + 1] = -1.0f;
    outc[r * 3 + 2] = -1.0f;
}

// Winner resolution: last point index wins per (row, offset) slot
__global__ void winnerK(const int* __restrict__ coords, int n) {
    int i = blockIdx.x * blockDim.x + threadIdx.x;
    if (i >= n) return;
    int x = coords[3 * i + 0];
    int y = coords[3 * i + 1];
    int z = coords[3 * i + 2];
    unsigned key = ((unsigned)(x >> 1) << 14) | ((unsigned)(y >> 1) << 7) | (unsigned)(z >> 1);
    unsigned row = g_rank[key];
    int off = (x & 1) * 4 + (y & 1) * 2 + (z & 1);
    atomicMax(&g_winner[row * 8 + off], i);
}

// Gather: write every float4 of agg exactly once (no zero-fill pass).
// i indexes the n*32 float4s of agg. 4 consecutive threads share one winner
// slot; winner<0 (empty slot or padding row) -> zeros.
__global__ void gatherK(const float* __restrict__ feats,
                        float* __restrict__ agg, int total4) {
    int i = blockIdx.x * blockDim.x + threadIdx.x;
    if (i >= total4) return;
    int row = i >> 5;
    int q = i & 31;
    int w = g_winner[(row << 3) + (q >> 2)];
    float4 v = make_float4(0.f, 0.f, 0.f, 0.f);
    if (w >= 0) v = ((const float4*)feats)[(w << 2) + (q & 3)];
    ((float4*)agg)[i] = v;
}

// ---------------------------------------------------------------------------
extern "C" void kernel_launch(void* const* d_in, const int* in_sizes, int n_in,
                              void* d_out, int out_size) {
    const float* feats;
    const int* coords;
    int n;
    if (in_sizes[0] >= in_sizes[1]) {
        feats = (const float*)d_in[0];
        coords = (const int*)d_in[1];
        n = in_sizes[1] / 3;
    } else {
        feats = (const float*)d_in[1];
        coords = (const int*)d_in[0];
        n = in_sizes[0] / 3;
    }

    float* outc = (float*)d_out;            // [N,3] unique coords (as float)
    float* agg = outc + (size_t)n * 3;      // [N,128] aggregated features

    void* p_mark;   cudaGetSymbolAddress(&p_mark, g_mark);
    void* p_winner; cudaGetSymbolAddress(&p_winner, g_winner);

    cudaMemsetAsync(p_mark, 0, sizeof(unsigned int) * CELLS);
    cudaMemsetAsync(p_winner, 0xFF, sizeof(int) * 8 * (size_t)n);

    int tb = 256;
    markK<<<(n + tb - 1) / tb, tb>>>(coords, n);
    scanA<<<SCAN_BLOCKS, tb>>>();
    scanB<<<1, SCAN_BLOCKS>>>();
    scanC<<<SCAN_BLOCKS, tb>>>(outc);
    fillTailK<<<(n + tb - 1) / tb, tb>>>(outc, n);
    winnerK<<<(n + tb - 1) / tb, tb>>>(coords, n);
    int total4 = n * 32;                    // n*128 floats / 4
    gatherK<<<(total4 + tb - 1) / tb, tb>>>(feats, agg, total4);
}

// round 5
// speedup vs baseline: 1.1511x; 1.1511x over previous
#include <cuda_runtime.h>
#include <cstdint>

#define CELLS (1 << 21)        // 128^3 coarse cells, 21-bit key
#define NWORDS (CELLS / 32)    // 65536 bitmask words (256 KB, L2-resident)
#define NBLOCKS 64             // scan blocks: 64 x 256 thr x 4 words
#define MAXN 524288

__device__ __align__(16) unsigned g_mask[NWORDS];   // occupancy bitmask
__device__ __align__(16) unsigned g_wpre[NWORDS];   // exclusive popc prefix per word
__device__ unsigned g_bsum[NBLOCKS];
__device__ unsigned g_numu;
__device__ int g_winner[MAXN * 8];

// ---------------------------------------------------------------------------
__global__ void markK(const int* __restrict__ coords, int n) {
    int i = blockIdx.x * blockDim.x + threadIdx.x;
    if (i >= n) return;
    int cx = coords[3 * i + 0] >> 1;
    int cy = coords[3 * i + 1] >> 1;
    int cz = coords[3 * i + 2] >> 1;
    unsigned key = ((unsigned)cx << 14) | ((unsigned)cy << 7) | (unsigned)cz;
    atomicOr(&g_mask[key >> 5], 1u << (key & 31));
}

// Stage A: per-block popcount sums (64 blocks x 256 thr x 4 words)
__global__ void scanA() {
    int t = threadIdx.x, lane = t & 31, warp = t >> 5;
    const uint4* p = (const uint4*)&g_mask[blockIdx.x * 1024 + t * 4];
    uint4 a = p[0];
    unsigned sum = __popc(a.x) + __popc(a.y) + __popc(a.z) + __popc(a.w);
#pragma unroll
    for (int o = 16; o > 0; o >>= 1) sum += __shfl_down_sync(0xFFFFFFFFu, sum, o);
    __shared__ unsigned ws[8];
    if (lane == 0) ws[warp] = sum;
    __syncthreads();
    if (t == 0) {
        unsigned s = 0;
#pragma unroll
        for (int i = 0; i < 8; i++) s += ws[i];
        g_bsum[blockIdx.x] = s;
    }
}

// Stage B+C fused: per-word exclusive prefix -> g_wpre, plus direct emission
// of the sorted unique coarse coords (mask + rank already in registers).
__global__ void scanC(float* __restrict__ outc) {
    int t = threadIdx.x, lane = t & 31, warp = t >> 5;
    int wbase = blockIdx.x * 1024 + t * 4;
    const uint4* p = (const uint4*)&g_mask[wbase];
    uint4 a = p[0];
    unsigned w0 = a.x, w1 = a.y, w2 = a.z, w3 = a.w;
    unsigned csum = __popc(w0) + __popc(w1) + __popc(w2) + __popc(w3);

    // warp inclusive scan of per-thread counts
    unsigned incl = csum;
#pragma unroll
    for (int o = 1; o < 32; o <<= 1) {
        unsigned y = __shfl_up_sync(0xFFFFFFFFu, incl, o);
        if (lane >= o) incl += y;
    }
    __shared__ unsigned wsum[8];
    __shared__ unsigned sbase;
    if (lane == 31) wsum[warp] = incl;
    __syncthreads();
    if (warp == 0) {
        // cross-block exclusive base: sum of g_bsum[j < blockIdx.x]
        unsigned v = 0;
        if (lane < (int)blockIdx.x) v += g_bsum[lane];
        if (lane + 32 < (int)blockIdx.x) v += g_bsum[lane + 32];
#pragma unroll
        for (int o = 16; o > 0; o >>= 1) v += __shfl_down_sync(0xFFFFFFFFu, v, o);
        if (lane == 0) sbase = v;
        // inclusive scan of the 8 warp sums
        if (lane < 8) {
            unsigned w = wsum[lane];
#pragma unroll
            for (int o = 1; o < 8; o <<= 1) {
                unsigned y = __shfl_up_sync(0x000000FFu, w, o);
                if (lane >= o) w += y;
            }
            wsum[lane] = w;
        }
    }
    __syncthreads();
    unsigned run = sbase + (warp ? wsum[warp - 1] : 0u) + (incl - csum);

    unsigned words[4] = {w0, w1, w2, w3};
    uint4 pre;
    unsigned* pp = &pre.x;
#pragma unroll
    for (int i = 0; i < 4; i++) {
        pp[i] = run;
        unsigned m = words[i];
        unsigned r = run;
        unsigned kb = (unsigned)(wbase + i) << 5;
        while (m) {
            unsigned b = (unsigned)__ffs(m) - 1u;
            m &= m - 1u;
            unsigned key = kb + b;
            outc[r * 3 + 0] = (float)(key >> 14);
            outc[r * 3 + 1] = (float)((key >> 7) & 127);
            outc[r * 3 + 2] = (float)(key & 127);
            r++;
        }
        run += __popc(words[i]);
    }
    ((uint4*)&g_wpre[wbase])[0] = pre;
    if (blockIdx.x == NBLOCKS - 1 && t == 255) g_numu = run;
}

// Fill only the padding rows (row >= numu) with -1
__global__ void fillTailK(float* __restrict__ outc, int n) {
    int r = blockIdx.x * blockDim.x + threadIdx.x;
    if (r >= n || (unsigned)r < g_numu) return;
    outc[r * 3 + 0] = -1.0f;
    outc[r * 3 + 1] = -1.0f;
    outc[r * 3 + 2] = -1.0f;
}

__device__ __forceinline__ unsigned rank_of(unsigned key) {
    unsigned w = key >> 5, b = key & 31;
    return g_wpre[w] + __popc(g_mask[w] & ((1u << b) - 1u));
}

// Winner resolution: last point index wins per (row, offset) slot
__global__ void winnerK(const int* __restrict__ coords, int n) {
    int i = blockIdx.x * blockDim.x + threadIdx.x;
    if (i >= n) return;
    int x = coords[3 * i + 0];
    int y = coords[3 * i + 1];
    int z = coords[3 * i + 2];
    unsigned key = ((unsigned)(x >> 1) << 14) | ((unsigned)(y >> 1) << 7) | (unsigned)(z >> 1);
    unsigned row = rank_of(key);
    int off = (x & 1) * 4 + (y & 1) * 2 + (z & 1);
    atomicMax(&g_winner[row * 8 + off], i);
}

// Scatter features: 4 threads per point, one float4 each (coalesced reads,
// 64B scattered writes). Rank lookups are L2-resident (512 KB tables).
__global__ void scatterK(const float* __restrict__ feats,
                         const int* __restrict__ coords,
                         float* __restrict__ agg, int n) {
    int j = blockIdx.x * blockDim.x + threadIdx.x;
    int i = j >> 2;
    int q = j & 3;
    if (i >= n) return;
    int x = coords[3 * i + 0];
    int y = coords[3 * i + 1];
    int z = coords[3 * i + 2];
    unsigned key = ((unsigned)(x >> 1) << 14) | ((unsigned)(y >> 1) << 7) | (unsigned)(z >> 1);
    unsigned row = rank_of(key);
    int off = (x & 1) * 4 + (y & 1) * 2 + (z & 1);
    if (g_winner[row * 8 + off] != i) return;  // deterministic last-wins
    float4 v = ((const float4*)feats)[i * 4 + q];
    ((float4*)agg)[(row * 128 + off * 16) / 4 + q] = v;
}

// ---------------------------------------------------------------------------
extern "C" void kernel_launch(void* const* d_in, const int* in_sizes, int n_in,
                              void* d_out, int out_size) {
    const float* feats;
    const int* coords;
    int n;
    if (in_sizes[0] >= in_sizes[1]) {
        feats = (const float*)d_in[0];
        coords = (const int*)d_in[1];
        n = in_sizes[1] / 3;
    } else {
        feats = (const float*)d_in[1];
        coords = (const int*)d_in[0];
        n = in_sizes[0] / 3;
    }

    float* outc = (float*)d_out;            // [N,3] unique coords (as float)
    float* agg = outc + (size_t)n * 3;      // [N,128] aggregated features

    void* p_mask;   cudaGetSymbolAddress(&p_mask, g_mask);
    void* p_winner; cudaGetSymbolAddress(&p_winner, g_winner);

    cudaMemsetAsync(agg, 0, sizeof(float) * 128 * (size_t)n);
    cudaMemsetAsync(p_mask, 0, sizeof(unsigned) * NWORDS);
    cudaMemsetAsync(p_winner, 0xFF, sizeof(int) * 8 * (size_t)n);

    int tb = 256;
    markK<<<(n + tb - 1) / tb, tb>>>(coords, n);
    scanA<<<NBLOCKS, tb>>>();
    scanC<<<NBLOCKS, tb>>>(outc);
    fillTailK<<<(n + tb - 1) / tb, tb>>>(outc, n);
    winnerK<<<(n + tb - 1) / tb, tb>>>(coords, n);
    scatterK<<<(n * 4 + tb - 1) / tb, tb>>>(feats, coords, agg, n);
}